// round 11
// baseline (speedup 1.0000x reference)
#include <cuda_runtime.h>
#include <cuda_fp16.h>
#include <math.h>
#include <stdint.h>

#define NH   8
#define S    4096
#define FIN  128
#define FOUT 64
#define SW   128   // adjacency words per row (4096/32)

// ------------------------- device scratch (no allocs) -----------------------
__device__ __half   g_hT[NH*FOUT*S];   // 4 MB fp16 transposed features [h][o][j]
__device__ float4   g_fp[NH*S];        // (f1, e^f1, e^{0.2 f1}, 0) per (h,i)
__device__ float    g_f2[NH*S];
__device__ float    g_D1[NH*S], g_D2[NH*S];
__device__ float4   g_fc[NH*S];        // (f2, Q1/den, Q2/den, 0) per (h,j)
__device__ uint2    g_adjbits2[S*SW/2];  // 2 MB bit-packed adjacency

// ------------------------- helpers ------------------------------------------
__device__ __forceinline__ uint32_t smem_u32(const void* p) {
    uint32_t a;
    asm("{ .reg .u64 t; cvta.to.shared.u64 t, %1; cvt.u32.u64 %0, t; }" : "=r"(a) : "l"(p));
    return a;
}
// pack two f32 -> f16x2 (lo = x, hi = y), single cvt
__device__ __forceinline__ uint32_t pack2(float x, float y) {
    uint32_t r;
    asm("cvt.rn.f16x2.f32 %0, %1, %2;" : "=r"(r) : "f"(y), "f"(x));
    return r;
}
// f16-accumulator HMMA: d packed as 2x half2 {c0c1, c2c3}
__device__ __forceinline__ void mma16h(uint32_t* d, const uint32_t* a,
                                       uint32_t b0, uint32_t b1) {
    asm volatile("mma.sync.aligned.m16n8k16.row.col.f16.f16.f16.f16 "
        "{%0,%1}, {%2,%3,%4,%5}, {%6,%7}, {%0,%1};"
        : "+r"(d[0]), "+r"(d[1])
        : "r"(a[0]), "r"(a[1]), "r"(a[2]), "r"(a[3]), "r"(b0), "r"(b1));
}
// attention weight (f32; fp16 rounding happens at pack2)
__device__ __forceinline__ float wgen(float f1, float p1, float p2,
                                      const float4 fc, unsigned wb, int sh) {
    float t  = f1 + fc.x;
    bool  pt = t > 0.f;
    float av = pt ? p1 : p2;
    float bv = pt ? fc.y : fc.z;
    float w  = av * bv;
    return ((wb >> sh) & 1u) ? w : 0.f;
}
#define CP_ASYNC16(dst, src) \
    asm volatile("cp.async.cg.shared.global [%0], [%1], 16;" :: "r"(dst), "l"(src))
#define CP_ASYNC8(dst, src) \
    asm volatile("cp.async.ca.shared.global [%0], [%1], 8;" :: "r"(dst), "l"(src))
#define CP_COMMIT()  asm volatile("cp.async.commit_group;" ::: "memory")
#define CP_WAIT(n)   asm volatile("cp.async.wait_group %0;" :: "n"(n) : "memory")

// ---------------------------------------------------------------------------
// Fused prep: blocks 0..511 do the projection GEMM; blocks 512..1023 pack the
// adjacency bitmask + zero D1/D2. DRAM-bound pack overlaps compute-bound proj.
__global__ void __launch_bounds__(256) k_prep(const float* __restrict__ X,
                                              const float* __restrict__ W,
                                              const float* __restrict__ a1,
                                              const float* __restrict__ a2,
                                              const int* __restrict__ adj) {
    __shared__ float  Xs[64][65];
    __shared__ float  Ws[64][64];
    __shared__ float  red1[64][4], red2[64][4];
    __shared__ __half Ht[64][72];
    int tid = threadIdx.x;

    if (blockIdx.x >= 512) {
        // ---------------- pack role ----------------
        int pb = blockIdx.x - 512;
        int gt = pb * 256 + tid;
        if (gt < NH*S) { g_D1[gt] = 0.f; g_D2[gt] = 0.f; }
        int row  = gt >> 5;                    // 8 rows per block
        int lane = tid & 31;
        const int* arow = adj + (size_t)row * S;
        unsigned*  brow = (unsigned*)(g_adjbits2 + (size_t)row * (SW/2));
        #pragma unroll 8
        for (int wd = 0; wd < SW; wd++) {
            int v = arow[wd*32 + lane];
            unsigned m = __ballot_sync(0xffffffffu, v != 0);
            if (lane == 0) brow[wd] = m;
        }
        return;
    }
    // ---------------- projection role ----------------
    int h  = blockIdx.x >> 6;
    int i0 = (blockIdx.x & 63) << 6;
    int il = tid >> 2, oq = tid & 3;
    float acc[16];
    #pragma unroll
    for (int u = 0; u < 16; u++) acc[u] = 0.f;

    for (int kc = 0; kc < 2; kc++) {
        __syncthreads();
        #pragma unroll
        for (int r = 0; r < 16; r++) {
            int idx = tid + 256*r;
            int rr = idx >> 6, c = idx & 63;
            Xs[rr][c] = X[(i0+rr)*FIN + kc*64 + c];
            Ws[rr][c] = W[h*FIN*FOUT + (kc*64+rr)*FOUT + c];
        }
        __syncthreads();
        #pragma unroll 4
        for (int k = 0; k < 64; k++) {
            float xv = Xs[il][k];
            #pragma unroll
            for (int g = 0; g < 4; g++) {
                float4 w4 = *(const float4*)&Ws[k][oq*16 + g*4];
                acc[g*4+0] += xv*w4.x; acc[g*4+1] += xv*w4.y;
                acc[g*4+2] += xv*w4.z; acc[g*4+3] += xv*w4.w;
            }
        }
    }
    int i = i0 + il;
    float p1 = 0.f, p2 = 0.f;
    #pragma unroll
    for (int u = 0; u < 16; u++) {
        int o = oq*16 + u;
        p1 += acc[u] * a1[h*FOUT + o];
        p2 += acc[u] * a2[h*FOUT + o];
        Ht[o][il] = __float2half_rn(acc[u]);
    }
    red1[il][oq] = p1; red2[il][oq] = p2;
    __syncthreads();
    if (oq == 0) {
        float f1 = red1[il][0]+red1[il][1]+red1[il][2]+red1[il][3];
        float f2 = red2[il][0]+red2[il][1]+red2[il][2]+red2[il][3];
        g_f2[h*S+i] = f2;
        g_fp[h*S+i] = make_float4(f1, expf(f1), expf(0.2f*f1), 0.f);
    }
    // coalesced transposed write
    {
        int o = tid >> 2, q = tid & 3;
        const uint4* src = (const uint4*)&Ht[o][q*16];
        uint4* dst = (uint4*)(g_hT + (size_t)(h*FOUT + o)*S + i0 + q*16);
        dst[0] = src[0];
        dst[1] = src[1];
    }
}

// ---------------------------------------------------------------------------
// Column-denominator pass (softmax over source axis i for fixed sink j).
__global__ void __launch_bounds__(256) k_passA() {
    int jc = blockIdx.x & 31;
    int ic = blockIdx.x >> 5;
    int j0 = jc << 7, i0 = ic << 8;
    __shared__ float4 fps[NH][256];    // 32 KB
    __shared__ uint4  bits4[256];      //  4 KB
    int tid = threadIdx.x;
    #pragma unroll
    for (int r = 0; r < 8; r++) {
        int idx = tid + 256*r;
        int hh = idx >> 8, ii = idx & 255;
        fps[hh][ii] = g_fp[hh*S + i0 + ii];
    }
    const unsigned* ab = (const unsigned*)g_adjbits2;
    {
        unsigned* b = (unsigned*)bits4;
        #pragma unroll
        for (int r = 0; r < 4; r++) {
            int idx = tid + 256*r;
            b[idx] = ab[(i0 + (idx>>2))*SW + jc*4 + (idx&3)];
        }
    }
    __syncthreads();

    const int hh  = tid >> 5;          // warp-uniform head
    const int jsh = tid & 31;
    float acc1[4], acc2[4], f2v[4];
    #pragma unroll
    for (int p = 0; p < 4; p++) {
        f2v[p] = g_f2[hh*S + j0 + p*32 + jsh];
        acc1[p] = 0.f; acc2[p] = 0.f;
    }
    for (int ii = 0; ii < 256; ii++) {
        uint4  wv = bits4[ii];           // broadcast
        float4 v  = fps[hh][ii];         // warp broadcast
        unsigned wd[4] = {wv.x, wv.y, wv.z, wv.w};
        #pragma unroll
        for (int p = 0; p < 4; p++) {
            float bf = (float)((wd[p] >> jsh) & 1u);
            float t  = v.x + f2v[p];
            float m1 = (t > 0.f) ? bf : 0.f;
            acc1[p] = fmaf(m1,      v.y, acc1[p]);
            acc2[p] = fmaf(bf - m1, v.z, acc2[p]);
        }
    }
    #pragma unroll
    for (int p = 0; p < 4; p++) {
        atomicAdd(&g_D1[hh*S + j0 + p*32 + jsh], acc1[p]);
        atomicAdd(&g_D2[hh*S + j0 + p*32 + jsh], acc2[p]);
    }
}

// ---------------------------------------------------------------------------
__global__ void k_combine() {
    int idx = blockIdx.x*blockDim.x + threadIdx.x;
    if (idx >= NH*S) return;
    float f2 = g_f2[idx];
    float q1 = expf(f2), q2 = expf(0.2f*f2);
    float d  = q1*g_D1[idx] + q2*g_D2[idx];
    float r  = (d > 0.f) ? 1.f/d : 0.f;
    g_fc[idx] = make_float4(f2, q1*r, q2*r, 0.f);
}

// ---------------------------------------------------------------------------
// Main contraction: m16n8k16 fp16 with **f16 accumulator** (2x tensor rate if
// legacy mode honors it), promoted to f32 every 64-j chunk. 128-row i-tiles,
// 8 warps x 16 rows, 2 CTAs/SM; 3-deep cp.async pipeline; XOR-swizzled B.
__global__ void __launch_bounds__(256, 2) k_main_mma(float* __restrict__ out) {
    __shared__ uint32_t Bsh[3][64*32];   // 24 KB
    __shared__ float4   fcs[3][64];      //  3 KB
    __shared__ uint2    bits_s[3][128];  //  3 KB
    const int tid  = threadIdx.x;
    const int lane = tid & 31, wid = tid >> 5;
    const int h    = blockIdx.x >> 5;
    const int i0   = (blockIdx.x & 31) << 7;
    const int lr   = lane >> 2, lc = lane & 3;

    const uint32_t sb_b  = smem_u32(Bsh);
    const uint32_t sb_fc = smem_u32(fcs);
    const uint32_t sb_bt = smem_u32(bits_s);
    const __half*  hb    = g_hT + (size_t)(h*FOUT)*S;

    float f1r[2], p1r[2], p2r[2];
    #pragma unroll
    for (int q2 = 0; q2 < 2; q2++) {
        int r = i0 + wid*16 + q2*8 + lr;
        float4 v = g_fp[h*S + r];
        f1r[q2] = v.x; p1r[q2] = v.y; p2r[q2] = v.z;
    }
    float acc[8][4];
    #pragma unroll
    for (int nb = 0; nb < 8; nb++)
        #pragma unroll
        for (int u = 0; u < 4; u++) acc[nb][u] = 0.f;

    auto issue_chunk = [&](int c) {
        const int buf = c % 3, j0 = c << 6;
        #pragma unroll
        for (int g = 0; g < 2; g++) {
            int lin = g*256 + tid;
            int n = lin >> 3, pb = lin & 7;
            uint32_t wofs = (uint32_t)(n*32 + ((pb*4) ^ ((4*n) & 31)));
            CP_ASYNC16(sb_b + (uint32_t)buf*8192 + wofs*4,
                       hb + (size_t)n*S + j0 + pb*8);
        }
        if (tid < 64)
            CP_ASYNC16(sb_fc + (uint32_t)(buf*64 + tid)*16, &g_fc[h*S + j0 + tid]);
        if (tid < 128)
            CP_ASYNC8(sb_bt + (uint32_t)(buf*128 + tid)*8,
                      &g_adjbits2[(size_t)(i0 + tid)*(SW/2) + c]);
        CP_COMMIT();
    };

    issue_chunk(0); issue_chunk(1); issue_chunk(2);
    for (int c = 0; c < S/64; c++) {
        if (c <= 61) CP_WAIT(2); else if (c == 62) CP_WAIT(1); else CP_WAIT(0);
        __syncthreads();
        const int buf = c % 3;
        uint2 bw0 = bits_s[buf][wid*16 + lr];
        uint2 bw1 = bits_s[buf][wid*16 + 8 + lr];
        const uint32_t* Bw = Bsh[buf];
        uint32_t acch[8][2];                      // f16x2 chunk accumulators
        #pragma unroll
        for (int nb = 0; nb < 8; nb++) { acch[nb][0] = 0u; acch[nb][1] = 0u; }
        #pragma unroll
        for (int ks = 0; ks < 4; ks++) {
            const int jb = ks*16;
            const float4 f0  = fcs[buf][jb + 2*lc];
            const float4 f1_ = fcs[buf][jb + 2*lc + 1];
            const float4 f8  = fcs[buf][jb + 2*lc + 8];
            const float4 f9  = fcs[buf][jb + 2*lc + 9];
            const int  sh  = (jb & 31) + 2*lc;
            const bool hiw = jb >= 32;
            unsigned w0 = hiw ? bw0.y : bw0.x;
            unsigned w1 = hiw ? bw1.y : bw1.x;
            uint32_t a[4];
            a[0] = pack2(wgen(f1r[0], p1r[0], p2r[0], f0,  w0, sh),
                         wgen(f1r[0], p1r[0], p2r[0], f1_, w0, sh + 1));
            a[1] = pack2(wgen(f1r[1], p1r[1], p2r[1], f0,  w1, sh),
                         wgen(f1r[1], p1r[1], p2r[1], f1_, w1, sh + 1));
            a[2] = pack2(wgen(f1r[0], p1r[0], p2r[0], f8,  w0, sh + 8),
                         wgen(f1r[0], p1r[0], p2r[0], f9,  w0, sh + 9));
            a[3] = pack2(wgen(f1r[1], p1r[1], p2r[1], f8,  w1, sh + 8),
                         wgen(f1r[1], p1r[1], p2r[1], f9,  w1, sh + 9));
            const int p0 = ks*8 + lc, p1 = p0 + 4;
            #pragma unroll
            for (int nb = 0; nb < 8; nb++) {
                int n = nb*8 + lr;
                uint32_t msk = (4*n) & 31;
                uint32_t b0 = Bw[n*32 + (p0 ^ msk)];
                uint32_t b1 = Bw[n*32 + (p1 ^ msk)];
                mma16h(acch[nb], a, b0, b1);
            }
        }
        // promote chunk partials to f32
        #pragma unroll
        for (int nb = 0; nb < 8; nb++) {
            float2 lo = __half22float2(*(__half2*)&acch[nb][0]);
            float2 hi = __half22float2(*(__half2*)&acch[nb][1]);
            acc[nb][0] += lo.x; acc[nb][1] += lo.y;
            acc[nb][2] += hi.x; acc[nb][3] += hi.y;
        }
        __syncthreads();
        if (c + 3 < S/64) issue_chunk(c + 3);
    }
    // ---- epilogue: ELU + store
    {
        int rbase = i0 + wid*16 + lr;
        #pragma unroll
        for (int nb = 0; nb < 8; nb++) {
            int n = h*FOUT + nb*8 + lc*2;
            float v0 = acc[nb][0], v1 = acc[nb][1];
            float v2 = acc[nb][2], v3 = acc[nb][3];
            float2 lo = make_float2(v0 > 0.f ? v0 : expm1f(v0),
                                    v1 > 0.f ? v1 : expm1f(v1));
            float2 hi = make_float2(v2 > 0.f ? v2 : expm1f(v2),
                                    v3 > 0.f ? v3 : expm1f(v3));
            *(float2*)&out[(size_t)rbase*(NH*FOUT) + n]       = lo;
            *(float2*)&out[(size_t)(rbase + 8)*(NH*FOUT) + n] = hi;
        }
    }
}

// ---------------------------------------------------------------------------
extern "C" void kernel_launch(void* const* d_in, const int* in_sizes, int n_in,
                              void* d_out, int out_size) {
    const float* X   = (const float*)d_in[0];   // [1,4096,128]
    const int*   adj = (const int*)  d_in[1];   // [1,4096,4096]
    const float* W   = (const float*)d_in[2];   // [8,128,64]
    const float* a1  = (const float*)d_in[3];   // [8,64,1]
    const float* a2  = (const float*)d_in[4];   // [8,64,1]
    float* out = (float*)d_out;                 // [4096,512]

    k_prep    <<<1024, 256>>>(X, W, a1, a2, adj);
    k_passA   <<<512, 256>>>();
    k_combine <<<128, 256>>>();
    k_main_mma<<<256, 256>>>(out);
}

// round 15
// speedup vs baseline: 1.0707x; 1.0707x over previous
#include <cuda_runtime.h>
#include <cuda_fp16.h>
#include <math.h>
#include <stdint.h>

#define NH   8
#define S    4096
#define FIN  128
#define FOUT 64
#define SW   128   // adjacency words per row (4096/32)

// ------------------------- device scratch (no allocs) -----------------------
__device__ __half   g_hT[NH*FOUT*S];   // 4 MB fp16 transposed features [h][o][j]
__device__ float4   g_fp[NH*S];        // (f1, e^f1, e^{0.2 f1}, 0) per (h,i)
__device__ float    g_f2[NH*S];
__device__ float    g_D1[NH*S], g_D2[NH*S];
__device__ uint4    g_fcH[NH*S/2];     // per jpair: {f2x2, c1x2, c2x2, 0} f16x2
__device__ uint2    g_adjbits2[S*SW/2];  // 2 MB bit-packed adjacency

// ------------------------- helpers ------------------------------------------
__device__ __forceinline__ uint32_t smem_u32(const void* p) {
    uint32_t a;
    asm("{ .reg .u64 t; cvta.to.shared.u64 t, %1; cvt.u32.u64 %0, t; }" : "=r"(a) : "l"(p));
    return a;
}
// pack two f32 -> f16x2 (lo = x, hi = y), single cvt
__device__ __forceinline__ uint32_t pack2(float x, float y) {
    uint32_t r;
    asm("cvt.rn.f16x2.f32 %0, %1, %2;" : "=r"(r) : "f"(y), "f"(x));
    return r;
}
// f32-accumulator HMMA
__device__ __forceinline__ void mma16(float* d, const uint32_t* a, uint32_t b0, uint32_t b1) {
    asm volatile("mma.sync.aligned.m16n8k16.row.col.f32.f16.f16.f32 "
        "{%0,%1,%2,%3}, {%4,%5,%6,%7}, {%8,%9}, {%0,%1,%2,%3};"
        : "+f"(d[0]), "+f"(d[1]), "+f"(d[2]), "+f"(d[3])
        : "r"(a[0]), "r"(a[1]), "r"(a[2]), "r"(a[3]), "r"(b0), "r"(b1));
}
// half2 A-fragment gen: 2 attention weights in one f16x2 register.
// fc = {f2x2, c1x2, c2x2, -}; wrd = adjacency word; sh = bit pos of even j.
__device__ __forceinline__ uint32_t agen(uint32_t f1_2, uint32_t p1_2, uint32_t p2_2,
                                         const uint4 fc, unsigned wrd, int sh) {
    uint32_t t2, mpos, prod1, prod2;
    asm("add.rn.f16x2 %0, %1, %2;" : "=r"(t2) : "r"(f1_2), "r"(fc.x));
    asm("set.gt.u32.f16x2 %0, %1, %2;" : "=r"(mpos) : "r"(t2), "r"(0u));
    asm("mul.rn.f16x2 %0, %1, %2;" : "=r"(prod1) : "r"(p1_2), "r"(fc.y));
    asm("mul.rn.f16x2 %0, %1, %2;" : "=r"(prod2) : "r"(p2_2), "r"(fc.z));
    unsigned e = (wrd >> sh) & 3u;
    uint32_t madj = ((e & 1u) ? 0x0000FFFFu : 0u) | ((e & 2u) ? 0xFFFF0000u : 0u);
    uint32_t r = (prod1 & mpos) | (prod2 & ~mpos);
    return r & madj;
}
#define CP_ASYNC16(dst, src) \
    asm volatile("cp.async.cg.shared.global [%0], [%1], 16;" :: "r"(dst), "l"(src))
#define CP_ASYNC8(dst, src) \
    asm volatile("cp.async.ca.shared.global [%0], [%1], 8;" :: "r"(dst), "l"(src))
#define CP_COMMIT()  asm volatile("cp.async.commit_group;" ::: "memory")
#define CP_WAIT(n)   asm volatile("cp.async.wait_group %0;" :: "n"(n) : "memory")

// ---------------------------------------------------------------------------
// Fused prep: blocks 0..511 projection GEMM; blocks 512..1023 pack adjacency
// bitmask + zero D1/D2 (DRAM-bound pack overlaps compute-bound proj).
__global__ void __launch_bounds__(256) k_prep(const float* __restrict__ X,
                                              const float* __restrict__ W,
                                              const float* __restrict__ a1,
                                              const float* __restrict__ a2,
                                              const int* __restrict__ adj) {
    __shared__ float  Xs[64][65];
    __shared__ float  Ws[64][64];
    __shared__ float  red1[64][4], red2[64][4];
    __shared__ __half Ht[64][72];
    int tid = threadIdx.x;

    if (blockIdx.x >= 512) {
        int pb = blockIdx.x - 512;
        int gt = pb * 256 + tid;
        if (gt < NH*S) { g_D1[gt] = 0.f; g_D2[gt] = 0.f; }
        int row  = gt >> 5;
        int lane = tid & 31;
        const int* arow = adj + (size_t)row * S;
        unsigned*  brow = (unsigned*)(g_adjbits2 + (size_t)row * (SW/2));
        #pragma unroll 8
        for (int wd = 0; wd < SW; wd++) {
            int v = arow[wd*32 + lane];
            unsigned m = __ballot_sync(0xffffffffu, v != 0);
            if (lane == 0) brow[wd] = m;
        }
        return;
    }
    int h  = blockIdx.x >> 6;
    int i0 = (blockIdx.x & 63) << 6;
    int il = tid >> 2, oq = tid & 3;
    float acc[16];
    #pragma unroll
    for (int u = 0; u < 16; u++) acc[u] = 0.f;

    for (int kc = 0; kc < 2; kc++) {
        __syncthreads();
        #pragma unroll
        for (int r = 0; r < 16; r++) {
            int idx = tid + 256*r;
            int rr = idx >> 6, c = idx & 63;
            Xs[rr][c] = X[(i0+rr)*FIN + kc*64 + c];
            Ws[rr][c] = W[h*FIN*FOUT + (kc*64+rr)*FOUT + c];
        }
        __syncthreads();
        #pragma unroll 4
        for (int k = 0; k < 64; k++) {
            float xv = Xs[il][k];
            #pragma unroll
            for (int g = 0; g < 4; g++) {
                float4 w4 = *(const float4*)&Ws[k][oq*16 + g*4];
                acc[g*4+0] += xv*w4.x; acc[g*4+1] += xv*w4.y;
                acc[g*4+2] += xv*w4.z; acc[g*4+3] += xv*w4.w;
            }
        }
    }
    int i = i0 + il;
    float p1 = 0.f, p2 = 0.f;
    #pragma unroll
    for (int u = 0; u < 16; u++) {
        int o = oq*16 + u;
        p1 += acc[u] * a1[h*FOUT + o];
        p2 += acc[u] * a2[h*FOUT + o];
        Ht[o][il] = __float2half_rn(acc[u]);
    }
    red1[il][oq] = p1; red2[il][oq] = p2;
    __syncthreads();
    if (oq == 0) {
        float f1 = red1[il][0]+red1[il][1]+red1[il][2]+red1[il][3];
        float f2 = red2[il][0]+red2[il][1]+red2[il][2]+red2[il][3];
        g_f2[h*S+i] = f2;
        g_fp[h*S+i] = make_float4(f1, expf(f1), expf(0.2f*f1), 0.f);
    }
    {
        int o = tid >> 2, q = tid & 3;
        const uint4* src = (const uint4*)&Ht[o][q*16];
        uint4* dst = (uint4*)(g_hT + (size_t)(h*FOUT + o)*S + i0 + q*16);
        dst[0] = src[0];
        dst[1] = src[1];
    }
}

// ---------------------------------------------------------------------------
// Column-denominator pass (softmax over source axis i for fixed sink j).
__global__ void __launch_bounds__(256) k_passA() {
    int jc = blockIdx.x & 31;
    int ic = blockIdx.x >> 5;
    int j0 = jc << 7, i0 = ic << 8;
    __shared__ float4 fps[NH][256];    // 32 KB
    __shared__ uint4  bits4[256];      //  4 KB
    int tid = threadIdx.x;
    #pragma unroll
    for (int r = 0; r < 8; r++) {
        int idx = tid + 256*r;
        int hh = idx >> 8, ii = idx & 255;
        fps[hh][ii] = g_fp[hh*S + i0 + ii];
    }
    const unsigned* ab = (const unsigned*)g_adjbits2;
    {
        unsigned* b = (unsigned*)bits4;
        #pragma unroll
        for (int r = 0; r < 4; r++) {
            int idx = tid + 256*r;
            b[idx] = ab[(i0 + (idx>>2))*SW + jc*4 + (idx&3)];
        }
    }
    __syncthreads();

    const int hh  = tid >> 5;          // warp-uniform head
    const int jsh = tid & 31;
    float acc1[4], acc2[4], f2v[4];
    #pragma unroll
    for (int p = 0; p < 4; p++) {
        f2v[p] = g_f2[hh*S + j0 + p*32 + jsh];
        acc1[p] = 0.f; acc2[p] = 0.f;
    }
    for (int ii = 0; ii < 256; ii++) {
        uint4  wv = bits4[ii];           // broadcast
        float4 v  = fps[hh][ii];         // warp broadcast
        unsigned wd[4] = {wv.x, wv.y, wv.z, wv.w};
        #pragma unroll
        for (int p = 0; p < 4; p++) {
            float bf = (float)((wd[p] >> jsh) & 1u);
            float t  = v.x + f2v[p];
            float m1 = (t > 0.f) ? bf : 0.f;
            acc1[p] = fmaf(m1,      v.y, acc1[p]);
            acc2[p] = fmaf(bf - m1, v.z, acc2[p]);
        }
    }
    #pragma unroll
    for (int p = 0; p < 4; p++) {
        atomicAdd(&g_D1[hh*S + j0 + p*32 + jsh], acc1[p]);
        atomicAdd(&g_D2[hh*S + j0 + p*32 + jsh], acc2[p]);
    }
}

// ---------------------------------------------------------------------------
// Pack per-jpair softmax factors as f16x2: {f2x2, (Q1/den)x2, (Q2/den)x2, 0}.
__global__ void k_combine() {
    int idx = blockIdx.x*blockDim.x + threadIdx.x;   // jpair index
    if (idx >= NH*S/2) return;
    int j = idx*2;
    float f2a = g_f2[j],   f2b = g_f2[j+1];
    float q1a = expf(f2a), q2a = expf(0.2f*f2a);
    float q1b = expf(f2b), q2b = expf(0.2f*f2b);
    float da  = q1a*g_D1[j]   + q2a*g_D2[j];
    float db  = q1b*g_D1[j+1] + q2b*g_D2[j+1];
    float ra  = (da > 0.f) ? 1.f/da : 0.f;
    float rb  = (db > 0.f) ? 1.f/db : 0.f;
    uint4 v;
    v.x = pack2(f2a, f2b);
    v.y = pack2(q1a*ra, q1b*rb);
    v.z = pack2(q2a*ra, q2b*rb);
    v.w = 0u;
    g_fcH[idx] = v;
}

// ---------------------------------------------------------------------------
// Main contraction (mma.sync m16n8k16 fp16, f32 accum): half2 A-generation,
// 128-row i-tiles, 8 warps x 16 rows, 2 CTAs/SM; 3-deep cp.async pipeline.
__global__ void __launch_bounds__(256, 2) k_main_mma(float* __restrict__ out) {
    __shared__ uint32_t Bsh[3][64*32];   // 24 KB (XOR-swizzled f16x2 words)
    __shared__ uint4    fcs[3][32];      //  1.5 KB (per-jpair factors)
    __shared__ uint2    bits_s[3][128];  //  3 KB
    const int tid  = threadIdx.x;
    const int lane = tid & 31, wid = tid >> 5;
    const int h    = blockIdx.x >> 5;
    const int i0   = (blockIdx.x & 31) << 7;
    const int lr   = lane >> 2, lc = lane & 3;

    const uint32_t sb_b  = smem_u32(Bsh);
    const uint32_t sb_fc = smem_u32(fcs);
    const uint32_t sb_bt = smem_u32(bits_s);
    const __half*  hb    = g_hT + (size_t)(h*FOUT)*S;

    // Per-thread row constants as half2 broadcasts (rows lr, lr+8 of warp tile)
    uint32_t f1h[2], p1h[2], p2h[2];
    #pragma unroll
    for (int q2 = 0; q2 < 2; q2++) {
        int r = i0 + wid*16 + q2*8 + lr;
        float4 v = g_fp[h*S + r];
        f1h[q2] = pack2(v.x, v.x);
        p1h[q2] = pack2(v.y, v.y);
        p2h[q2] = pack2(v.z, v.z);
    }
    float acc[8][4];
    #pragma unroll
    for (int nb = 0; nb < 8; nb++)
        #pragma unroll
        for (int u = 0; u < 4; u++) acc[nb][u] = 0.f;

    auto issue_chunk = [&](int c) {
        const int buf = c % 3, j0 = c << 6;
        #pragma unroll
        for (int g = 0; g < 2; g++) {
            int lin = g*256 + tid;
            int n = lin >> 3, pb = lin & 7;
            uint32_t wofs = (uint32_t)(n*32 + ((pb*4) ^ ((4*n) & 31)));
            CP_ASYNC16(sb_b + (uint32_t)buf*8192 + wofs*4,
                       hb + (size_t)n*S + j0 + pb*8);
        }
        if (tid < 32)
            CP_ASYNC16(sb_fc + (uint32_t)(buf*32 + tid)*16,
                       &g_fcH[(size_t)(h*S >> 1) + (j0 >> 1) + tid]);
        if (tid < 128)
            CP_ASYNC8(sb_bt + (uint32_t)(buf*128 + tid)*8,
                      &g_adjbits2[(size_t)(i0 + tid)*(SW/2) + c]);
        CP_COMMIT();
    };

    issue_chunk(0); issue_chunk(1); issue_chunk(2);
    for (int c = 0; c < S/64; c++) {
        if (c <= 61) CP_WAIT(2); else if (c == 62) CP_WAIT(1); else CP_WAIT(0);
        __syncthreads();
        const int buf = c % 3;
        uint2 bw0 = bits_s[buf][wid*16 + lr];        // row lr
        uint2 bw1 = bits_s[buf][wid*16 + 8 + lr];    // row lr+8
        const uint32_t* Bw = Bsh[buf];
        #pragma unroll
        for (int ks = 0; ks < 4; ks++) {
            const uint4 fc0 = fcs[buf][ks*8 + lc];       // jpair for j = jb+2lc
            const uint4 fc1 = fcs[buf][ks*8 + lc + 4];   // jpair for j = jb+2lc+8
            const unsigned wrd0 = (ks < 2) ? bw0.x : bw0.y;
            const unsigned wrd1 = (ks < 2) ? bw1.x : bw1.y;
            const int sh = ((ks & 1) << 4) + 2*lc;
            uint32_t a[4];
            a[0] = agen(f1h[0], p1h[0], p2h[0], fc0, wrd0, sh);
            a[1] = agen(f1h[1], p1h[1], p2h[1], fc0, wrd1, sh);
            a[2] = agen(f1h[0], p1h[0], p2h[0], fc1, wrd0, sh + 8);
            a[3] = agen(f1h[1], p1h[1], p2h[1], fc1, wrd1, sh + 8);
            const int p0 = ks*8 + lc, p1 = p0 + 4;
            #pragma unroll
            for (int nb = 0; nb < 8; nb++) {
                int n = nb*8 + lr;
                uint32_t msk = (4*n) & 31;
                uint32_t b0 = Bw[n*32 + (p0 ^ msk)];
                uint32_t b1 = Bw[n*32 + (p1 ^ msk)];
                mma16(acc[nb], a, b0, b1);
            }
        }
        __syncthreads();
        if (c + 3 < S/64) issue_chunk(c + 3);
    }
    // ---- epilogue: ELU + store
    {
        int rbase = i0 + wid*16 + lr;
        #pragma unroll
        for (int nb = 0; nb < 8; nb++) {
            int n = h*FOUT + nb*8 + lc*2;
            float v0 = acc[nb][0], v1 = acc[nb][1];
            float v2 = acc[nb][2], v3 = acc[nb][3];
            float2 lo = make_float2(v0 > 0.f ? v0 : expm1f(v0),
                                    v1 > 0.f ? v1 : expm1f(v1));
            float2 hi = make_float2(v2 > 0.f ? v2 : expm1f(v2),
                                    v3 > 0.f ? v3 : expm1f(v3));
            *(float2*)&out[(size_t)rbase*(NH*FOUT) + n]       = lo;
            *(float2*)&out[(size_t)(rbase + 8)*(NH*FOUT) + n] = hi;
        }
    }
}

// ---------------------------------------------------------------------------
extern "C" void kernel_launch(void* const* d_in, const int* in_sizes, int n_in,
                              void* d_out, int out_size) {
    const float* X   = (const float*)d_in[0];   // [1,4096,128]
    const int*   adj = (const int*)  d_in[1];   // [1,4096,4096]
    const float* W   = (const float*)d_in[2];   // [8,128,64]
    const float* a1  = (const float*)d_in[3];   // [8,64,1]
    const float* a2  = (const float*)d_in[4];   // [8,64,1]
    float* out = (float*)d_out;                 // [4096,512]

    k_prep    <<<1024, 256>>>(X, W, a1, a2, adj);
    k_passA   <<<512, 256>>>();
    k_combine <<<64, 256>>>();
    k_main_mma<<<256, 256>>>(out);
}